// round 10
// baseline (speedup 1.0000x reference)
#include <cuda_runtime.h>

#define N_NODES 100000
#define IN_C    128
#define HC      256
#define NHEAD   4
#define CDIM    64
#define NE      1600000
#define NEG     0.2f
#define BNEPS   1e-5f

// ---- device scratch (allocation-free: __device__ globals) ----
__device__ float g_h[N_NODES * HC];          // projected features  [N,256]
__device__ float g_asrc[N_NODES * NHEAD];    // per-node src logits [N,4]
__device__ float g_adst[N_NODES * NHEAD];    // per-node dst logits [N,4]
__device__ int   g_cnt[N_NODES];             // in-degree histogram
__device__ int   g_rowptr[N_NODES + 1];      // CSR row pointers (by dst)
__device__ int   g_fill[N_NODES];            // fill cursors
__device__ int   g_csr[NE];                  // src ids grouped by dst
__device__ int   g_part[128];                // scan partials
__device__ int   g_part2[128];
__device__ float g_stat[2 * HC];             // per-channel sum / sumsq
__device__ float g_scale[HC];
__device__ float g_shift[HC];
__device__ int   g_i64;                      // 1 if edge_index is int64

// ---------------------------------------------------------------------------
__global__ void probe_kernel(const int* __restrict__ ei32) {
    int v = 0;
    for (int k = 0; k < 1024; k++) v |= ei32[2 * k + 1];
    g_i64 = (v == 0) ? 1 : 0;
}

__device__ __forceinline__ int load_edge(const void* ei, int idx) {
    if (g_i64) return (int)((const long long*)ei)[idx];
    return ((const int*)ei)[idx];
}

// ---------------------------------------------------------------------------
__global__ void init_kernel() {
    int i = blockIdx.x * blockDim.x + threadIdx.x;
    if (i < N_NODES) g_cnt[i] = 0;
    if (i < 2 * HC)  g_stat[i] = 0.f;
}

// ---------------------------------------------------------------------------
// GEMM: g_h = x @ W (100000x128 @ 128x256), 64x256 block tile, 8x8 thread
// tile computed as 8x4 packed f32x2 pairs via fma.rn.f32x2 (FFMA2: 2 FMAs
// per instruction -> 2x fp32 throughput vs 3-reg FFMA on sm_103a).
// Fused a_src/a_dst epilogue (8-lane segmented shuffle reduce).
__global__ __launch_bounds__(256) void gemm_kernel(const float* __restrict__ x,
                                                   const float* __restrict__ W,
                                                   const float* __restrict__ att_src,
                                                   const float* __restrict__ att_dst) {
    __shared__ float Ws[16][256];
    __shared__ float Xs[16][64];
    const int rowbase = blockIdx.x * 64;
    const int tid = threadIdx.x;
    const int ty = tid >> 5;
    const int tx = tid & 31;

    unsigned long long acc2[8][4];   // acc2[i][j] = (acc[i][2j], acc[i][2j+1])
    #pragma unroll
    for (int i = 0; i < 8; i++)
        #pragma unroll
        for (int j = 0; j < 4; j++) acc2[i][j] = 0ull;

    for (int k0 = 0; k0 < IN_C; k0 += 16) {
        #pragma unroll
        for (int i = 0; i < 4; i++) {
            int idx = tid + i * 256;
            int k = idx >> 6, c4 = idx & 63;
            float4 w = *(const float4*)(W + (k0 + k) * 256 + c4 * 4);
            *(float4*)(&Ws[k][c4 * 4]) = w;
        }
        {
            int r = tid >> 2, kq = tid & 3;
            int row = rowbase + r;
            float4 xv = make_float4(0.f, 0.f, 0.f, 0.f);
            if (row < N_NODES)
                xv = *(const float4*)(x + row * IN_C + k0 + kq * 4);
            Xs[kq * 4 + 0][r] = xv.x; Xs[kq * 4 + 1][r] = xv.y;
            Xs[kq * 4 + 2][r] = xv.z; Xs[kq * 4 + 3][r] = xv.w;
        }
        __syncthreads();
        #pragma unroll
        for (int k = 0; k < 16; k++) {
            float xf[8];
            *(float4*)(xf)     = *(float4*)&Xs[k][ty * 8];
            *(float4*)(xf + 4) = *(float4*)&Xs[k][ty * 8 + 4];
            // W pairs load directly packed (adjacent floats = one f32x2)
            ulonglong2 wa = *(ulonglong2*)&Ws[k][tx * 8];
            ulonglong2 wb = *(ulonglong2*)&Ws[k][tx * 8 + 4];
            unsigned long long wp0 = wa.x, wp1 = wa.y, wp2 = wb.x, wp3 = wb.y;
            #pragma unroll
            for (int i = 0; i < 8; i++) {
                unsigned long long xd;
                asm("mov.b64 %0, {%1, %1};" : "=l"(xd) : "f"(xf[i]));
                asm("fma.rn.f32x2 %0, %1, %2, %0;" : "+l"(acc2[i][0]) : "l"(xd), "l"(wp0));
                asm("fma.rn.f32x2 %0, %1, %2, %0;" : "+l"(acc2[i][1]) : "l"(xd), "l"(wp1));
                asm("fma.rn.f32x2 %0, %1, %2, %0;" : "+l"(acc2[i][2]) : "l"(xd), "l"(wp2));
                asm("fma.rn.f32x2 %0, %1, %2, %0;" : "+l"(acc2[i][3]) : "l"(xd), "l"(wp3));
            }
        }
        __syncthreads();
    }

    float ats[8], atd[8];
    *(float4*)(ats)     = *(const float4*)(att_src + tx * 8);
    *(float4*)(ats + 4) = *(const float4*)(att_src + tx * 8 + 4);
    *(float4*)(atd)     = *(const float4*)(att_dst + tx * 8);
    *(float4*)(atd + 4) = *(const float4*)(att_dst + tx * 8 + 4);
    const int head = tx >> 3;

    #pragma unroll
    for (int i = 0; i < 8; i++) {
        float acc[8];
        #pragma unroll
        for (int j = 0; j < 4; j++)
            asm("mov.b64 {%0, %1}, %2;"
                : "=f"(acc[2 * j]), "=f"(acc[2 * j + 1]) : "l"(acc2[i][j]));

        int row = rowbase + ty * 8 + i;
        if (row < N_NODES) {
            *(float4*)(g_h + row * 256 + tx * 8)     = *(float4*)(acc);
            *(float4*)(g_h + row * 256 + tx * 8 + 4) = *(float4*)(acc + 4);
        }
        float as = 0.f, ad = 0.f;
        #pragma unroll
        for (int j = 0; j < 8; j++) {
            as += acc[j] * ats[j];
            ad += acc[j] * atd[j];
        }
        #pragma unroll
        for (int o = 4; o; o >>= 1) {
            as += __shfl_down_sync(0xFFFFFFFFu, as, o, 8);
            ad += __shfl_down_sync(0xFFFFFFFFu, ad, o, 8);
        }
        if ((tx & 7) == 0 && row < N_NODES) {
            g_asrc[row * 4 + head] = as;
            g_adst[row * 4 + head] = ad;
        }
    }
}

// ---------------------------------------------------------------------------
__global__ void hist_kernel(const void* __restrict__ ei) {
    int i = blockIdx.x * blockDim.x + threadIdx.x;
    if (i < NE) {
        int d = load_edge(ei, NE + i);
        if ((unsigned)d < (unsigned)N_NODES) atomicAdd(&g_cnt[d], 1);
    }
}

__global__ __launch_bounds__(1024) void scan1_kernel() {
    __shared__ int sh[1024];
    int i = blockIdx.x * 1024 + threadIdx.x;
    int v = (i < N_NODES) ? g_cnt[i] : 0;
    sh[threadIdx.x] = v; __syncthreads();
    for (int off = 1; off < 1024; off <<= 1) {
        int t = (threadIdx.x >= off) ? sh[threadIdx.x - off] : 0;
        __syncthreads();
        sh[threadIdx.x] += t; __syncthreads();
    }
    if (i < N_NODES) g_rowptr[i] = sh[threadIdx.x] - v;  // exclusive
    if (threadIdx.x == 1023) g_part[blockIdx.x] = sh[1023];
}

__global__ __launch_bounds__(128) void scan2_kernel(int nb) {
    __shared__ int sh[128];
    int v = (threadIdx.x < nb) ? g_part[threadIdx.x] : 0;
    sh[threadIdx.x] = v; __syncthreads();
    for (int off = 1; off < 128; off <<= 1) {
        int t = (threadIdx.x >= off) ? sh[threadIdx.x - off] : 0;
        __syncthreads();
        sh[threadIdx.x] += t; __syncthreads();
    }
    if (threadIdx.x < nb) g_part2[threadIdx.x] = sh[threadIdx.x] - v;
    if (threadIdx.x == nb - 1) g_rowptr[N_NODES] = sh[threadIdx.x]; // total valid
}

__global__ __launch_bounds__(1024) void scan3_kernel() {
    int i = blockIdx.x * 1024 + threadIdx.x;
    if (i < N_NODES) {
        int v = g_rowptr[i] + g_part2[blockIdx.x];
        g_rowptr[i] = v;
        g_fill[i] = v;
    }
}

__global__ void fill_kernel(const void* __restrict__ ei) {
    int i = blockIdx.x * blockDim.x + threadIdx.x;
    if (i < NE) {
        int s = load_edge(ei, i);
        int d = load_edge(ei, NE + i);
        if ((unsigned)s < (unsigned)N_NODES && (unsigned)d < (unsigned)N_NODES) {
            int pos = atomicAdd(&g_fill[d], 1);
            g_csr[pos] = s;
        }
    }
}

// ---------------------------------------------------------------------------
// Aggregate: one WARP per (node, head). 8 warps/block = 2 nodes. No shared
// memory, no block syncs. Each warp owns 64 channels (2 floats/lane).
__global__ __launch_bounds__(256) void agg_kernel(const float* __restrict__ bias,
                                                  float* __restrict__ out) {
    const int warp = threadIdx.x >> 5;
    const int lane = threadIdx.x & 31;
    const int node = blockIdx.x * 2 + (warp >> 2);
    const int hd   = warp & 3;
    if (node >= N_NODES) return;

    const int ebase = g_rowptr[node];
    const int deg   = g_rowptr[node + 1] - ebase;
    const float adh = g_adst[node * 4 + hd];
    const int   off = hd * 64;

    // denominator (includes self-loop)
    float e = g_asrc[node * 4 + hd] + adh;
    e = e > 0.f ? e : NEG * e;
    const float exself = __expf(e);
    float den = (lane == 0) ? exself : 0.f;
    for (int j = lane; j < deg; j += 32) {
        int s = g_csr[ebase + j];
        float t = g_asrc[s * 4 + hd] + adh;
        t = t > 0.f ? t : NEG * t;
        den += __expf(t);
    }
    #pragma unroll
    for (int o = 16; o; o >>= 1) den += __shfl_xor_sync(0xFFFFFFFFu, den, o);
    const float inv = 1.f / (den + 1e-16f);

    // self contribution
    const float selfw = exself * inv;
    const float* hi = g_h + (size_t)node * 256 + off;
    float x0 = hi[lane] * selfw,       x1 = 0.f;
    float y0 = hi[lane + 32] * selfw,  y1 = 0.f;

    for (int base = 0; base < deg; base += 32) {
        const int m = min(32, deg - base);
        int   sl = 0; float al = 0.f;
        if (lane < m) {
            sl = g_csr[ebase + base + lane];
            float t = g_asrc[sl * 4 + hd] + adh;
            t = t > 0.f ? t : NEG * t;
            al = __expf(t) * inv;
        }
        int k = 0;
        for (; k + 4 <= m; k += 4) {
            int   s0 = __shfl_sync(0xFFFFFFFFu, sl, k);
            int   s1 = __shfl_sync(0xFFFFFFFFu, sl, k + 1);
            int   s2 = __shfl_sync(0xFFFFFFFFu, sl, k + 2);
            int   s3 = __shfl_sync(0xFFFFFFFFu, sl, k + 3);
            float w0 = __shfl_sync(0xFFFFFFFFu, al, k);
            float w1 = __shfl_sync(0xFFFFFFFFu, al, k + 1);
            float w2 = __shfl_sync(0xFFFFFFFFu, al, k + 2);
            float w3 = __shfl_sync(0xFFFFFFFFu, al, k + 3);
            const float* p0 = g_h + (size_t)s0 * 256 + off;
            const float* p1 = g_h + (size_t)s1 * 256 + off;
            const float* p2 = g_h + (size_t)s2 * 256 + off;
            const float* p3 = g_h + (size_t)s3 * 256 + off;
            x0 += p0[lane] * w0;  y0 += p0[lane + 32] * w0;
            x1 += p1[lane] * w1;  y1 += p1[lane + 32] * w1;
            x0 += p2[lane] * w2;  y0 += p2[lane + 32] * w2;
            x1 += p3[lane] * w3;  y1 += p3[lane + 32] * w3;
        }
        for (; k < m; k++) {
            int   s0 = __shfl_sync(0xFFFFFFFFu, sl, k);
            float w0 = __shfl_sync(0xFFFFFFFFu, al, k);
            const float* p0 = g_h + (size_t)s0 * 256 + off;
            x0 += p0[lane] * w0;  y0 += p0[lane + 32] * w0;
        }
    }
    float* po = out + (size_t)node * 256 + off;
    po[lane]      = x0 + x1 + bias[off + lane];
    po[lane + 32] = y0 + y1 + bias[off + lane + 32];
}

// ---------------------------------------------------------------------------
__global__ __launch_bounds__(256) void bnstat_kernel(const float* __restrict__ out) {
    int t = threadIdx.x;
    int r0 = blockIdx.x * 256;
    int rmax = min(256, N_NODES - r0);
    float s = 0.f, s2 = 0.f;
    for (int r = 0; r < rmax; r++) {
        float v = out[(size_t)(r0 + r) * 256 + t];
        s += v; s2 += v * v;
    }
    atomicAdd(&g_stat[t], s);
    atomicAdd(&g_stat[256 + t], s2);
}

__global__ __launch_bounds__(256) void bnfin_kernel(const float* __restrict__ gamma,
                                                    const float* __restrict__ beta) {
    int t = threadIdx.x;
    float invN = 1.f / (float)N_NODES;
    float mean = g_stat[t] * invN;
    float var = g_stat[256 + t] * invN - mean * mean;
    float sc = gamma[t] * rsqrtf(var + BNEPS);
    g_scale[t] = sc;
    g_shift[t] = beta[t] - mean * sc;
}

__global__ __launch_bounds__(256) void final_kernel(float* __restrict__ out) {
    int i4 = blockIdx.x * 256 + threadIdx.x;
    if (i4 >= N_NODES * (HC / 4)) return;
    int c = (i4 & 63) * 4;
    float4 v = ((float4*)out)[i4];
    float f;
    f = g_scale[c + 0] * v.x + g_shift[c + 0]; v.x = f > 0.f ? f : expm1f(f);
    f = g_scale[c + 1] * v.y + g_shift[c + 1]; v.y = f > 0.f ? f : expm1f(f);
    f = g_scale[c + 2] * v.z + g_shift[c + 2]; v.z = f > 0.f ? f : expm1f(f);
    f = g_scale[c + 3] * v.w + g_shift[c + 3]; v.w = f > 0.f ? f : expm1f(f);
    ((float4*)out)[i4] = v;
}

// ---------------------------------------------------------------------------
extern "C" void kernel_launch(void* const* d_in, const int* in_sizes, int n_in,
                              void* d_out, int out_size) {
    const float* x       = (const float*)d_in[0];
    const void*  ei      = d_in[1];
    const float* W       = (const float*)d_in[2];
    const float* att_src = (const float*)d_in[3];
    const float* att_dst = (const float*)d_in[4];
    const float* bias    = (const float*)d_in[5];
    const float* gamma   = (const float*)d_in[6];
    const float* beta    = (const float*)d_in[7];
    float* out = (float*)d_out;

    probe_kernel<<<1, 1>>>((const int*)ei);
    init_kernel<<<(N_NODES + 255) / 256, 256>>>();

    hist_kernel<<<(NE + 255) / 256, 256>>>(ei);
    gemm_kernel<<<(N_NODES + 63) / 64, 256>>>(x, W, att_src, att_dst);

    int nb = (N_NODES + 1023) / 1024;   // 98
    scan1_kernel<<<nb, 1024>>>();
    scan2_kernel<<<1, 128>>>(nb);
    scan3_kernel<<<nb, 1024>>>();
    fill_kernel<<<(NE + 255) / 256, 256>>>(ei);

    agg_kernel<<<(N_NODES + 1) / 2, 256>>>(bias, out);

    bnstat_kernel<<<(N_NODES + 255) / 256, 256>>>(out);
    bnfin_kernel<<<1, 256>>>(gamma, beta);
    final_kernel<<<(N_NODES * (HC / 4) + 255) / 256, 256>>>(out);
}

// round 12
// speedup vs baseline: 1.1261x; 1.1261x over previous
#include <cuda_runtime.h>

#define N_NODES 100000
#define IN_C    128
#define HC      256
#define NHEAD   4
#define CDIM    64
#define NE      1600000
#define NEG     0.2f
#define BNEPS   1e-5f

// ---- device scratch (allocation-free: __device__ globals) ----
__device__ float g_h[N_NODES * HC];          // projected features  [N,256]
__device__ float g_asrc[N_NODES * NHEAD];    // per-node src logits [N,4]
__device__ float g_adst[N_NODES * NHEAD];    // per-node dst logits [N,4]
__device__ int   g_cnt[N_NODES];             // in-degree histogram
__device__ int   g_rowptr[N_NODES + 1];      // CSR row pointers (by dst)
__device__ int   g_fill[N_NODES];            // fill cursors
__device__ int   g_csr[NE];                  // src ids grouped by dst
__device__ int   g_part[128];                // scan partials
__device__ int   g_part2[128];
__device__ float g_stat[2 * HC];             // per-channel sum / sumsq
__device__ float g_scale[HC];
__device__ float g_shift[HC];
__device__ int   g_i64;                      // 1 if edge_index is int64

// ---------------------------------------------------------------------------
__global__ void probe_kernel(const int* __restrict__ ei32) {
    int v = 0;
    for (int k = 0; k < 1024; k++) v |= ei32[2 * k + 1];
    g_i64 = (v == 0) ? 1 : 0;
}

__device__ __forceinline__ int load_edge(const void* ei, int idx) {
    if (g_i64) return (int)((const long long*)ei)[idx];
    return ((const int*)ei)[idx];
}

// ---------------------------------------------------------------------------
__global__ void init_kernel() {
    int i = blockIdx.x * blockDim.x + threadIdx.x;
    if (i < N_NODES) g_cnt[i] = 0;
    if (i < 2 * HC)  g_stat[i] = 0.f;
}

// ---------------------------------------------------------------------------
// GEMM: g_h = x @ W (100000x128 @ 128x256), 64x256 block tile.
// Thread tile 16 rows x 4 cols (acc pairs over ROWS so X loads packed f32x2
// straight from smem; W duplicated with 4 movs/k). Warp layout: rg=w&3 owns
// 16 rows, cg=w>>2 owns 128 cols (lane*4 within). W = 1 LDS.128/lane-k
// (halved vs 8x8 tiling), X = 4 broadcast LDS.128 -> smem crossbar pressure
// drops from 10 to 8 wavefronts per warp-k.
__global__ __launch_bounds__(256) void gemm_kernel(const float* __restrict__ x,
                                                   const float* __restrict__ W,
                                                   const float* __restrict__ att_src,
                                                   const float* __restrict__ att_dst) {
    __shared__ float Ws[16][256];
    __shared__ float Xs[16][64];
    const int rowbase = blockIdx.x * 64;
    const int tid  = threadIdx.x;
    const int w    = tid >> 5;
    const int lane = tid & 31;
    const int rg   = w & 3;                 // rows rg*16 .. +16
    const int colbase = (w >> 2) * 128 + lane * 4;

    unsigned long long acc2[8][4];          // [row-pair][col]
    #pragma unroll
    for (int rp = 0; rp < 8; rp++)
        #pragma unroll
        for (int c = 0; c < 4; c++) acc2[rp][c] = 0ull;

    for (int k0 = 0; k0 < IN_C; k0 += 16) {
        #pragma unroll
        for (int i = 0; i < 4; i++) {
            int idx = tid + i * 256;
            int k = idx >> 6, c4 = idx & 63;
            float4 wv = *(const float4*)(W + (k0 + k) * 256 + c4 * 4);
            *(float4*)(&Ws[k][c4 * 4]) = wv;
        }
        {
            int r = tid >> 2, kq = tid & 3;
            int row = rowbase + r;
            float4 xv = make_float4(0.f, 0.f, 0.f, 0.f);
            if (row < N_NODES)
                xv = *(const float4*)(x + row * IN_C + k0 + kq * 4);
            Xs[kq * 4 + 0][r] = xv.x; Xs[kq * 4 + 1][r] = xv.y;
            Xs[kq * 4 + 2][r] = xv.z; Xs[kq * 4 + 3][r] = xv.w;
        }
        __syncthreads();
        #pragma unroll
        for (int k = 0; k < 16; k++) {
            unsigned long long xd[8];
            #pragma unroll
            for (int rp = 0; rp < 8; rp++)
                xd[rp] = *(const unsigned long long*)&Xs[k][rg * 16 + 2 * rp];
            float4 wv = *(const float4*)&Ws[k][colbase];
            unsigned long long wd[4];
            asm("mov.b64 %0, {%1, %1};" : "=l"(wd[0]) : "f"(wv.x));
            asm("mov.b64 %0, {%1, %1};" : "=l"(wd[1]) : "f"(wv.y));
            asm("mov.b64 %0, {%1, %1};" : "=l"(wd[2]) : "f"(wv.z));
            asm("mov.b64 %0, {%1, %1};" : "=l"(wd[3]) : "f"(wv.w));
            #pragma unroll
            for (int rp = 0; rp < 8; rp++) {
                asm("fma.rn.f32x2 %0, %1, %2, %0;" : "+l"(acc2[rp][0]) : "l"(xd[rp]), "l"(wd[0]));
                asm("fma.rn.f32x2 %0, %1, %2, %0;" : "+l"(acc2[rp][1]) : "l"(xd[rp]), "l"(wd[1]));
                asm("fma.rn.f32x2 %0, %1, %2, %0;" : "+l"(acc2[rp][2]) : "l"(xd[rp]), "l"(wd[2]));
                asm("fma.rn.f32x2 %0, %1, %2, %0;" : "+l"(acc2[rp][3]) : "l"(xd[rp]), "l"(wd[3]));
            }
        }
        __syncthreads();
    }

    // epilogue: store + fused a_src/a_dst (16-lane segmented reduce per head)
    const float4 atsv = *(const float4*)(att_src + colbase);
    const float4 atdv = *(const float4*)(att_dst + colbase);
    const int head = colbase >> 6;          // cg*2 + lane/16

    #pragma unroll
    for (int rp = 0; rp < 8; rp++) {
        float r0[4], r1[4];
        #pragma unroll
        for (int c = 0; c < 4; c++)
            asm("mov.b64 {%0, %1}, %2;" : "=f"(r0[c]), "=f"(r1[c]) : "l"(acc2[rp][c]));
        int row0 = rowbase + rg * 16 + 2 * rp;
        int row1 = row0 + 1;
        if (row0 < N_NODES) *(float4*)(g_h + (size_t)row0 * 256 + colbase) = *(float4*)r0;
        if (row1 < N_NODES) *(float4*)(g_h + (size_t)row1 * 256 + colbase) = *(float4*)r1;

        float as0 = r0[0]*atsv.x + r0[1]*atsv.y + r0[2]*atsv.z + r0[3]*atsv.w;
        float ad0 = r0[0]*atdv.x + r0[1]*atdv.y + r0[2]*atdv.z + r0[3]*atdv.w;
        float as1 = r1[0]*atsv.x + r1[1]*atsv.y + r1[2]*atsv.z + r1[3]*atsv.w;
        float ad1 = r1[0]*atdv.x + r1[1]*atdv.y + r1[2]*atdv.z + r1[3]*atdv.w;
        #pragma unroll
        for (int o = 8; o; o >>= 1) {
            as0 += __shfl_down_sync(0xFFFFFFFFu, as0, o, 16);
            ad0 += __shfl_down_sync(0xFFFFFFFFu, ad0, o, 16);
            as1 += __shfl_down_sync(0xFFFFFFFFu, as1, o, 16);
            ad1 += __shfl_down_sync(0xFFFFFFFFu, ad1, o, 16);
        }
        if ((lane & 15) == 0) {
            if (row0 < N_NODES) { g_asrc[row0 * 4 + head] = as0; g_adst[row0 * 4 + head] = ad0; }
            if (row1 < N_NODES) { g_asrc[row1 * 4 + head] = as1; g_adst[row1 * 4 + head] = ad1; }
        }
    }
}

// ---------------------------------------------------------------------------
__global__ void hist_kernel(const void* __restrict__ ei) {
    int i = blockIdx.x * blockDim.x + threadIdx.x;
    if (i < NE) {
        int d = load_edge(ei, NE + i);
        if ((unsigned)d < (unsigned)N_NODES) atomicAdd(&g_cnt[d], 1);
    }
}

__global__ __launch_bounds__(1024) void scan1_kernel() {
    __shared__ int sh[1024];
    int i = blockIdx.x * 1024 + threadIdx.x;
    int v = (i < N_NODES) ? g_cnt[i] : 0;
    sh[threadIdx.x] = v; __syncthreads();
    for (int off = 1; off < 1024; off <<= 1) {
        int t = (threadIdx.x >= off) ? sh[threadIdx.x - off] : 0;
        __syncthreads();
        sh[threadIdx.x] += t; __syncthreads();
    }
    if (i < N_NODES) g_rowptr[i] = sh[threadIdx.x] - v;  // exclusive
    if (threadIdx.x == 1023) g_part[blockIdx.x] = sh[1023];
}

__global__ __launch_bounds__(128) void scan2_kernel(int nb) {
    __shared__ int sh[128];
    int v = (threadIdx.x < nb) ? g_part[threadIdx.x] : 0;
    sh[threadIdx.x] = v; __syncthreads();
    for (int off = 1; off < 128; off <<= 1) {
        int t = (threadIdx.x >= off) ? sh[threadIdx.x - off] : 0;
        __syncthreads();
        sh[threadIdx.x] += t; __syncthreads();
    }
    if (threadIdx.x < nb) g_part2[threadIdx.x] = sh[threadIdx.x] - v;
    if (threadIdx.x == nb - 1) g_rowptr[N_NODES] = sh[threadIdx.x]; // total valid
}

__global__ __launch_bounds__(1024) void scan3_kernel() {
    int i = blockIdx.x * 1024 + threadIdx.x;
    if (i < N_NODES) {
        int v = g_rowptr[i] + g_part2[blockIdx.x];
        g_rowptr[i] = v;
        g_fill[i] = v;
    }
}

__global__ void fill_kernel(const void* __restrict__ ei) {
    int i = blockIdx.x * blockDim.x + threadIdx.x;
    if (i < NE) {
        int s = load_edge(ei, i);
        int d = load_edge(ei, NE + i);
        if ((unsigned)s < (unsigned)N_NODES && (unsigned)d < (unsigned)N_NODES) {
            int pos = atomicAdd(&g_fill[d], 1);
            g_csr[pos] = s;
        }
    }
}

// ---------------------------------------------------------------------------
// Aggregate: one WARP per (node, head), SINGLE pass. Softmax normalization
// commutes with the weighted sum: accumulate unnormalized exp-weights and
// their sum simultaneously, divide once at the end. Halves csr/asrc traffic.
__global__ __launch_bounds__(256) void agg_kernel(const float* __restrict__ bias,
                                                  float* __restrict__ out) {
    const int warp = threadIdx.x >> 5;
    const int lane = threadIdx.x & 31;
    const int node = blockIdx.x * 2 + (warp >> 2);
    const int hd   = warp & 3;
    if (node >= N_NODES) return;

    const int ebase = g_rowptr[node];
    const int deg   = g_rowptr[node + 1] - ebase;
    const float adh = g_adst[node * 4 + hd];
    const int   off = hd * 64;

    // self-loop (unnormalized)
    float e = g_asrc[node * 4 + hd] + adh;
    e = e > 0.f ? e : NEG * e;
    const float exself = __expf(e);

    const float* hi = g_h + (size_t)node * 256 + off;
    float x0 = hi[lane] * exself,      x1 = 0.f;
    float y0 = hi[lane + 32] * exself, y1 = 0.f;
    float den = 0.f;   // lane-local partial of edge exp-sum

    for (int base = 0; base < deg; base += 32) {
        const int m = min(32, deg - base);
        int   sl = 0; float al = 0.f;
        if (lane < m) {
            sl = g_csr[ebase + base + lane];
            float t = g_asrc[sl * 4 + hd] + adh;
            t = t > 0.f ? t : NEG * t;
            al = __expf(t);
        }
        den += al;
        int k = 0;
        for (; k + 4 <= m; k += 4) {
            int   s0 = __shfl_sync(0xFFFFFFFFu, sl, k);
            int   s1 = __shfl_sync(0xFFFFFFFFu, sl, k + 1);
            int   s2 = __shfl_sync(0xFFFFFFFFu, sl, k + 2);
            int   s3 = __shfl_sync(0xFFFFFFFFu, sl, k + 3);
            float w0 = __shfl_sync(0xFFFFFFFFu, al, k);
            float w1 = __shfl_sync(0xFFFFFFFFu, al, k + 1);
            float w2 = __shfl_sync(0xFFFFFFFFu, al, k + 2);
            float w3 = __shfl_sync(0xFFFFFFFFu, al, k + 3);
            const float* p0 = g_h + (size_t)s0 * 256 + off;
            const float* p1 = g_h + (size_t)s1 * 256 + off;
            const float* p2 = g_h + (size_t)s2 * 256 + off;
            const float* p3 = g_h + (size_t)s3 * 256 + off;
            x0 += p0[lane] * w0;  y0 += p0[lane + 32] * w0;
            x1 += p1[lane] * w1;  y1 += p1[lane + 32] * w1;
            x0 += p2[lane] * w2;  y0 += p2[lane + 32] * w2;
            x1 += p3[lane] * w3;  y1 += p3[lane + 32] * w3;
        }
        for (; k < m; k++) {
            int   s0 = __shfl_sync(0xFFFFFFFFu, sl, k);
            float w0 = __shfl_sync(0xFFFFFFFFu, al, k);
            const float* p0 = g_h + (size_t)s0 * 256 + off;
            x0 += p0[lane] * w0;  y0 += p0[lane + 32] * w0;
        }
    }
    #pragma unroll
    for (int o = 16; o; o >>= 1) den += __shfl_xor_sync(0xFFFFFFFFu, den, o);
    const float inv = 1.f / (den + exself + 1e-16f);

    float* po = out + (size_t)node * 256 + off;
    po[lane]      = (x0 + x1) * inv + bias[off + lane];
    po[lane + 32] = (y0 + y1) * inv + bias[off + lane + 32];
}

// ---------------------------------------------------------------------------
__global__ __launch_bounds__(256) void bnstat_kernel(const float* __restrict__ out) {
    int t = threadIdx.x;
    int r0 = blockIdx.x * 256;
    int rmax = min(256, N_NODES - r0);
    float s = 0.f, s2 = 0.f;
    for (int r = 0; r < rmax; r++) {
        float v = out[(size_t)(r0 + r) * 256 + t];
        s += v; s2 += v * v;
    }
    atomicAdd(&g_stat[t], s);
    atomicAdd(&g_stat[256 + t], s2);
}

__global__ __launch_bounds__(256) void bnfin_kernel(const float* __restrict__ gamma,
                                                    const float* __restrict__ beta) {
    int t = threadIdx.x;
    float invN = 1.f / (float)N_NODES;
    float mean = g_stat[t] * invN;
    float var = g_stat[256 + t] * invN - mean * mean;
    float sc = gamma[t] * rsqrtf(var + BNEPS);
    g_scale[t] = sc;
    g_shift[t] = beta[t] - mean * sc;
}

__global__ __launch_bounds__(256) void final_kernel(float* __restrict__ out) {
    int i4 = blockIdx.x * 256 + threadIdx.x;
    if (i4 >= N_NODES * (HC / 4)) return;
    int c = (i4 & 63) * 4;
    float4 v = ((float4*)out)[i4];
    float f;
    f = g_scale[c + 0] * v.x + g_shift[c + 0]; v.x = f > 0.f ? f : expm1f(f);
    f = g_scale[c + 1] * v.y + g_shift[c + 1]; v.y = f > 0.f ? f : expm1f(f);
    f = g_scale[c + 2] * v.z + g_shift[c + 2]; v.z = f > 0.f ? f : expm1f(f);
    f = g_scale[c + 3] * v.w + g_shift[c + 3]; v.w = f > 0.f ? f : expm1f(f);
    ((float4*)out)[i4] = v;
}

// ---------------------------------------------------------------------------
extern "C" void kernel_launch(void* const* d_in, const int* in_sizes, int n_in,
                              void* d_out, int out_size) {
    const float* x       = (const float*)d_in[0];
    const void*  ei      = d_in[1];
    const float* W       = (const float*)d_in[2];
    const float* att_src = (const float*)d_in[3];
    const float* att_dst = (const float*)d_in[4];
    const float* bias    = (const float*)d_in[5];
    const float* gamma   = (const float*)d_in[6];
    const float* beta    = (const float*)d_in[7];
    float* out = (float*)d_out;

    probe_kernel<<<1, 1>>>((const int*)ei);
    init_kernel<<<(N_NODES + 255) / 256, 256>>>();

    hist_kernel<<<(NE + 255) / 256, 256>>>(ei);
    gemm_kernel<<<(N_NODES + 63) / 64, 256>>>(x, W, att_src, att_dst);

    int nb = (N_NODES + 1023) / 1024;   // 98
    scan1_kernel<<<nb, 1024>>>();
    scan2_kernel<<<1, 128>>>(nb);
    scan3_kernel<<<nb, 1024>>>();
    fill_kernel<<<(NE + 255) / 256, 256>>>(ei);

    agg_kernel<<<(N_NODES + 1) / 2, 256>>>(bias, out);

    bnstat_kernel<<<(N_NODES + 255) / 256, 256>>>(out);
    bnfin_kernel<<<1, 256>>>(gamma, beta);
    final_kernel<<<(N_NODES * (HC / 4) + 255) / 256, 256>>>(out);
}